// round 1
// baseline (speedup 1.0000x reference)
#include <cuda_runtime.h>
#include <cuda_bf16.h>
#include <cstdint>

// Problem dims (fixed by setup_inputs)
#define HDIM 1024
#define ADIM 1024
#define EDIM 1024
#define SDIM 2048
#define VDIM 50257
#define NBOUND 25
#define MERGED (HDIM + ADIM)   // 2048

// ---------------- device scratch (no allocation allowed) ----------------
__device__ __align__(16) float g_h[2][HDIM];
__device__ __align__(16) float g_q[ADIM];
__device__ __align__(16) float g_s[SDIM];
__device__ __align__(16) float g_w[SDIM];
__device__ __align__(16) float g_ctx_part[8][ADIM];
__device__ __align__(16) float g_merge[MERGED];
__device__ __align__(16) float g_eproj[(size_t)SDIM * ADIM];  // 8 MB
__device__ int g_word;
__device__ unsigned long long g_argmax;

// ---------------- helpers ----------------
__device__ __forceinline__ float warp_sum(float v) {
#pragma unroll
    for (int o = 16; o; o >>= 1) v += __shfl_xor_sync(0xffffffffu, v, o);
    return v;
}

// FFMA-only 2^y (rel err ~1e-7); avoids MUFU pipe for the 2M tanh/step.
__device__ __forceinline__ float exp2_fast(float y) {
    y = fminf(fmaxf(y, -60.f), 60.f);
    float n = rintf(y);
    float f = y - n;
    float p = 1.5403530e-4f;
    p = fmaf(p, f, 1.3333558e-3f);
    p = fmaf(p, f, 9.6181291e-3f);
    p = fmaf(p, f, 5.5504109e-2f);
    p = fmaf(p, f, 2.4022651e-1f);
    p = fmaf(p, f, 6.9314718e-1f);
    p = fmaf(p, f, 1.0f);
    return __int_as_float(((int)n + 127) << 23) * p;
}
__device__ __forceinline__ float tanh_fast(float x) {
    float e = exp2_fast(x * 2.885390081777927f);   // e^(2x)
    return 1.f - 2.f / (e + 1.f);
}
__device__ __forceinline__ float sigmoid_fast(float x) {
    float e = exp2_fast(-1.4426950408889634f * x); // e^(-x)
    return 1.f / (1.f + e);
}

// ---------------- kernels ----------------
__global__ void k_init(const float* __restrict__ hidden) {
    for (int i = threadIdx.x; i < HDIM; i += blockDim.x) g_h[0][i] = hidden[i];
    if (threadIdx.x == 0) g_word = 1;  // SOS
}

// eproj[s,a] = sum_k emb[s,k] * W_e[a,k] + b_a[a]   (one-time 2048x1024x1024 GEMM)
__global__ void k_eproj(const float* __restrict__ emb, const float* __restrict__ We,
                        const float* __restrict__ ba) {
    __shared__ float As[32][33];
    __shared__ float Bs[32][33];
    int tx = threadIdx.x, ty = threadIdx.y;
    int srow = blockIdx.x * 32 + ty;
    int arow = blockIdx.y * 32 + ty;
    float acc = 0.f;
    for (int kt = 0; kt < EDIM; kt += 32) {
        As[ty][tx] = emb[(size_t)srow * EDIM + kt + tx];
        Bs[ty][tx] = We[(size_t)arow * EDIM + kt + tx];
        __syncthreads();
#pragma unroll
        for (int k = 0; k < 32; k++) acc = fmaf(As[ty][k], Bs[tx][k], acc);
        __syncthreads();
    }
    int a = blockIdx.y * 32 + tx;
    g_eproj[(size_t)srow * ADIM + a] = acc + ba[a];
}

// One block per hidden unit j: 6 warps compute the 6 dot products, thread 0 fuses gates.
__global__ void k_gru(const float* __restrict__ emb_table,
                      const float* __restrict__ W_ih, const float* __restrict__ W_hh,
                      const float* __restrict__ b_ih, const float* __restrict__ b_hh,
                      int pold) {
    int j = blockIdx.x;
    int w = threadIdx.x >> 5, lane = threadIdx.x & 31;
    __shared__ float dots[6];
    int word = g_word;
    const float* vec = (w < 3) ? (emb_table + (size_t)word * EDIM) : g_h[pold];
    const float* mat = (w < 3) ? (W_ih + (size_t)(w * HDIM + j) * EDIM)
                               : (W_hh + (size_t)((w - 3) * HDIM + j) * HDIM);
    const float4* m4 = (const float4*)mat;
    const float4* v4 = (const float4*)vec;
    float acc = 0.f;
#pragma unroll
    for (int i = 0; i < 8; i++) {
        float4 a = m4[lane + 32 * i];
        float4 b = v4[lane + 32 * i];
        acc = fmaf(a.x, b.x, acc); acc = fmaf(a.y, b.y, acc);
        acc = fmaf(a.z, b.z, acc); acc = fmaf(a.w, b.w, acc);
    }
    acc = warp_sum(acc);
    if (lane == 0) {
        float bia = (w < 3) ? b_ih[w * HDIM + j] : b_hh[(w - 3) * HDIM + j];
        dots[w] = acc + bia;
    }
    __syncthreads();
    if (threadIdx.x == 0) {
        float r = sigmoid_fast(dots[0] + dots[3]);
        float z = sigmoid_fast(dots[1] + dots[4]);
        float n = tanh_fast(dots[2] + r * dots[5]);
        float hold = g_h[pold][j];
        g_h[pold ^ 1][j] = (1.f - z) * n + z * hold;
    }
    // reset this step's argmax accumulator (runs well before k_vocab in-stream)
    if (blockIdx.x == 0 && threadIdx.x == 64) g_argmax = 0ull;
}

// q[a] = h_new . W_q[a,:]
__global__ void k_q(const float* __restrict__ Wq, int pnew) {
    __shared__ __align__(16) float hs[HDIM];
    for (int i = threadIdx.x; i < HDIM; i += 256) hs[i] = g_h[pnew][i];
    __syncthreads();
    int w = threadIdx.x >> 5, lane = threadIdx.x & 31;
    int a = blockIdx.x * 8 + w;
    const float4* m4 = (const float4*)(Wq + (size_t)a * HDIM);
    const float4* v4 = (const float4*)hs;
    float acc = 0.f;
#pragma unroll
    for (int i = 0; i < 8; i++) {
        float4 mm = m4[lane + 32 * i];
        float4 vv = v4[lane + 32 * i];
        acc = fmaf(mm.x, vv.x, acc); acc = fmaf(mm.y, vv.y, acc);
        acc = fmaf(mm.z, vv.z, acc); acc = fmaf(mm.w, vv.w, acc);
    }
    acc = warp_sum(acc);
    if (lane == 0) g_q[a] = acc;
}

// s[j] = sum_a tanh(eproj[j,a] + q[a]) * v_a[a]
__global__ void k_s(const float* __restrict__ va) {
    __shared__ __align__(16) float qs[ADIM];
    __shared__ __align__(16) float vs[ADIM];
    for (int i = threadIdx.x; i < ADIM; i += 256) { qs[i] = g_q[i]; vs[i] = va[i]; }
    __syncthreads();
    int w = threadIdx.x >> 5, lane = threadIdx.x & 31;
    int j = blockIdx.x * 8 + w;
    const float4* ep4 = (const float4*)(g_eproj + (size_t)j * ADIM);
    const float4* q4 = (const float4*)qs;
    const float4* v4 = (const float4*)vs;
    float acc = 0.f;
#pragma unroll
    for (int i = 0; i < 8; i++) {
        int k = lane + 32 * i;
        float4 e = ep4[k]; float4 q = q4[k]; float4 v = v4[k];
        acc = fmaf(tanh_fast(e.x + q.x), v.x, acc);
        acc = fmaf(tanh_fast(e.y + q.y), v.y, acc);
        acc = fmaf(tanh_fast(e.z + q.z), v.z, acc);
        acc = fmaf(tanh_fast(e.w + q.w), v.w, acc);
    }
    acc = warp_sum(acc);
    if (lane == 0) g_s[j] = acc;
}

// softmax over 2048 (one block), writes w + attention-weights output row
__global__ void k_softmax(float* __restrict__ out, int t) {
    int tid = threadIdx.x;
    int lane = tid & 31, wid = tid >> 5;
    __shared__ float red[32];
    float a0 = g_s[tid], a1 = g_s[tid + 1024];
    float m = fmaxf(a0, a1);
#pragma unroll
    for (int o = 16; o; o >>= 1) m = fmaxf(m, __shfl_xor_sync(0xffffffffu, m, o));
    if (lane == 0) red[wid] = m;
    __syncthreads();
    if (wid == 0) {
        float x = red[lane];
#pragma unroll
        for (int o = 16; o; o >>= 1) x = fmaxf(x, __shfl_xor_sync(0xffffffffu, x, o));
        red[lane] = x;
    }
    __syncthreads();
    m = red[0];
    float e0 = expf(a0 - m), e1 = expf(a1 - m);
    float ssum = e0 + e1;
#pragma unroll
    for (int o = 16; o; o >>= 1) ssum += __shfl_xor_sync(0xffffffffu, ssum, o);
    __syncthreads();
    if (lane == 0) red[wid] = ssum;
    __syncthreads();
    if (wid == 0) {
        float x = red[lane];
#pragma unroll
        for (int o = 16; o; o >>= 1) x += __shfl_xor_sync(0xffffffffu, x, o);
        red[lane] = x;
    }
    __syncthreads();
    float tot = red[0];
    float w0 = e0 / tot, w1 = e1 / tot;
    g_w[tid] = w0;
    g_w[tid + 1024] = w1;
    size_t base = (size_t)NBOUND + (size_t)t * SDIM;   // words first, then weights
    out[base + tid] = w0;
    out[base + tid + 1024] = w1;
}

// ctx partials: grid (4 a-blocks, 8 s-chunks)
__global__ void k_ctx(const float* __restrict__ e) {
    __shared__ float ws[256];
    int s0 = blockIdx.y * 256;
    ws[threadIdx.x] = g_w[s0 + threadIdx.x];
    __syncthreads();
    int a = blockIdx.x * 256 + threadIdx.x;
    float acc = 0.f;
#pragma unroll 4
    for (int s = 0; s < 256; s++)
        acc = fmaf(ws[s], e[(size_t)(s0 + s) * ADIM + a], acc);
    g_ctx_part[blockIdx.y][a] = acc;
}

__global__ void k_merge(int pnew) {
    int i = threadIdx.x;
    g_merge[i] = g_h[pnew][i];
    float c = 0.f;
#pragma unroll
    for (int p = 0; p < 8; p++) c += g_ctx_part[p][i];
    g_merge[HDIM + i] = c;
}

// vocab GEMV + argmax. One warp per row; __ldcs to keep small matrices L2-resident.
__global__ void k_vocab(const float* __restrict__ Wout, const float* __restrict__ bout) {
    __shared__ __align__(16) float ms[MERGED];
    for (int i = threadIdx.x; i < MERGED; i += 512) ms[i] = g_merge[i];
    __syncthreads();
    int w = threadIdx.x >> 5, lane = threadIdx.x & 31;
    int v = blockIdx.x * 16 + w;
    if (v < VDIM) {
        const float4* r4 = (const float4*)(Wout + (size_t)v * MERGED);
        const float4* m4 = (const float4*)ms;
        float acc = 0.f;
#pragma unroll
        for (int i = 0; i < 16; i++) {
            float4 rr = __ldcs(r4 + lane + 32 * i);
            float4 mm = m4[lane + 32 * i];
            acc = fmaf(rr.x, mm.x, acc); acc = fmaf(rr.y, mm.y, acc);
            acc = fmaf(rr.z, mm.z, acc); acc = fmaf(rr.w, mm.w, acc);
        }
        acc = warp_sum(acc);
        if (lane == 0) {
            float lg = acc + bout[v];
            unsigned u = __float_as_uint(lg);
            u = (u & 0x80000000u) ? ~u : (u | 0x80000000u);   // order-preserving encode
            // ties -> lower index wins (matches jnp.argmax first-max semantics)
            unsigned long long pk =
                ((unsigned long long)u << 32) | (unsigned long long)(0xFFFFFFFFu - (unsigned)v);
            atomicMax(&g_argmax, pk);
        }
    }
}

__global__ void k_decode(float* __restrict__ out, int t) {
    unsigned long long pk = g_argmax;
    int word = (int)(0xFFFFFFFFu - (unsigned)(pk & 0xFFFFFFFFull));
    g_word = word;
    out[t] = (float)word;   // words output (cast to output dtype float32)
}

// ---------------- launch ----------------
extern "C" void kernel_launch(void* const* d_in, const int* in_sizes, int n_in,
                              void* d_out, int out_size) {
    const float* hidden     = (const float*)d_in[0];
    const float* embeddings = (const float*)d_in[1];
    const float* emb_table  = (const float*)d_in[2];
    const float* W_ih       = (const float*)d_in[3];
    const float* W_hh       = (const float*)d_in[4];
    const float* b_ih       = (const float*)d_in[5];
    const float* b_hh       = (const float*)d_in[6];
    const float* W_e        = (const float*)d_in[7];
    const float* W_q        = (const float*)d_in[8];
    const float* b_a        = (const float*)d_in[9];
    const float* v_a        = (const float*)d_in[10];
    const float* W_out      = (const float*)d_in[11];
    const float* b_out      = (const float*)d_in[12];
    float* out = (float*)d_out;

    k_init<<<1, 256>>>(hidden);
    k_eproj<<<dim3(SDIM / 32, ADIM / 32), dim3(32, 32)>>>(embeddings, W_e, b_a);

    for (int t = 0; t < NBOUND; t++) {
        int pold = t & 1;
        int pnew = pold ^ 1;
        k_gru<<<1024, 192>>>(emb_table, W_ih, W_hh, b_ih, b_hh, pold);
        k_q<<<128, 256>>>(W_q, pnew);
        k_s<<<256, 256>>>(v_a);
        k_softmax<<<1, 1024>>>(out, t);
        k_ctx<<<dim3(4, 8), 256>>>(embeddings);
        k_merge<<<1, 1024>>>(pnew);
        k_vocab<<<(VDIM + 15) / 16, 512>>>(W_out, b_out);
        k_decode<<<1, 1>>>(out, t);
    }
}